// round 15
// baseline (speedup 1.0000x reference)
#include <cuda_runtime.h>
#include <cuda_bf16.h>
#include <math.h>

#define Bc 4
#define Lc 1536
#define Kc 30
#define EF 128
#define EIN 167
#define NSLOT 48   // Lc / 32

// GEMM k-dim after removing 16 pos dims: 151, padded to 152 = 76 k-pairs
#define KD 151
#define KPAD 152
#define KG 38      // 4-k groups

#define NTOPK (Bc*Lc/8)          // 768 topk blocks
#define PREP_TOTAL ((KPAD/2)*EF + 66*EF)
#define NPREP ((PREP_TOTAL + 255)/256)   // 71 prep blocks
#define NEDGE_BLOCKS 592         // 148 SMs x 4 resident blocks (persistent)

typedef unsigned long long ull;

// packed f32x2 FMA: acc.{lo,hi} += a.{lo,hi} * b.{lo,hi}
#define FMA_F32X2(acc, a, b) \
    asm("fma.rn.f32x2 %0, %1, %2, %0;" : "+l"(acc) : "l"(a), "l"(b))

// scratch (device globals; no allocation allowed)
__device__ float g_O[Bc*Lc*9];
__device__ int   g_Eidx[Bc*Lc*Kc];
__device__ float g_Dn[Bc*Lc*Kc];
__device__ __align__(16) ull g_WK[(KPAD/2)*EF];  // g_WK[kp][f] = {W[f][16+2kp], W[f][16+2kp+1]}
__device__ float g_T[66*EF];        // T[d][f] = sum_p (W_pos[p][d]+b_pos[p]) * W_edge[f][p]

// dist-pair maps: q=1..8 -> a-side base in s_misc, b-side offset
__device__ const int c_aoff[9] = {0, 12, 15, 12, 12, 9, 9, 15, 15};
__device__ const int c_boff[9] = {0, -1,  1,  0,  1, -1, 1, -1,  0};

// ---------------------------------------------------------------------------
// Kernel 1: [merged] prep blocks (>= NTOPK) + top-K/frames blocks (< NTOPK)
// ---------------------------------------------------------------------------
__global__ void __launch_bounds__(256)
k_topk(const float* __restrict__ Ca, const float* __restrict__ mask,
       const float* __restrict__ W, const float* __restrict__ W_pos,
       const float* __restrict__ b_pos,
       float* __restrict__ out, long long out_elems)
{
    int tid  = threadIdx.x;

    // ---------------- prep path (71 trailing blocks) ----------------
    if (blockIdx.x >= NTOPK) {
        int idx = (blockIdx.x - NTOPK) * 256 + tid;
        const int NW = (KPAD/2) * EF;    // 9728
        if (idx < NW) {
            int kp = idx >> 7;
            int f  = idx & (EF - 1);
            int k0 = 2 * kp, k1 = 2 * kp + 1;
            float w0 = (k0 < KD) ? W[f * EIN + 16 + k0] : 0.f;
            float w1 = (k1 < KD) ? W[f * EIN + 16 + k1] : 0.f;
            g_WK[idx] = ((ull)__float_as_uint(w1) << 32) | (ull)__float_as_uint(w0);
        } else {
            int j = idx - NW;            // 66*128 entries
            if (j < 66 * EF) {
                int d = j >> 7;
                int f = j & (EF - 1);
                float acc = 0.f;
                #pragma unroll
                for (int p = 0; p < 16; p++)
                    acc += (W_pos[p * 66 + d] + b_pos[p]) * W[f * EIN + p];
                g_T[d * EF + f] = acc;
            }
        }
        return;
    }

    // ---------------- top-K + frames path ----------------
    __shared__ float s_x[Lc], s_y[Lc], s_z[Lc], s_m[Lc];

    int warp = tid >> 5;
    int lane = tid & 31;
    int r0 = blockIdx.x * 8;
    int b  = r0 / Lc;
    const float* cab = Ca + (size_t)b * Lc * 3;
    const float* mb  = mask + (size_t)b * Lc;

    for (int idx = tid; idx < Lc; idx += 256) {
        s_x[idx] = cab[idx*3+0];
        s_y[idx] = cab[idx*3+1];
        s_z[idx] = cab[idx*3+2];
        s_m[idx] = mb[idx];
    }
    __syncthreads();

    // ---- fused frames for the block's 8 rows (threads 0..7) ----
    if (tid < 8) {
        int rr = r0 + tid;
        int ii = rr - b * Lc;
        float* O = &g_O[(size_t)rr * 9];
        if (ii < 1 || ii > Lc - 3) {
            #pragma unroll
            for (int t = 0; t < 9; t++) O[t] = 0.f;
        } else {
            float ax = s_x[ii] - s_x[ii-1], ay = s_y[ii] - s_y[ii-1], az = s_z[ii] - s_z[ii-1];
            float an = sqrtf(ax*ax + ay*ay + az*az + 1e-12f);
            float ab = (an > 3.6f && an < 4.0f) ? 1.f : 0.f;
            float u2x = ax*ab, u2y = ay*ab, u2z = az*ab;
            float rn2 = rsqrtf(u2x*u2x + u2y*u2y + u2z*u2z + 1e-12f);
            u2x *= rn2; u2y *= rn2; u2z *= rn2;

            float bx = s_x[ii+1] - s_x[ii], by = s_y[ii+1] - s_y[ii], bz = s_z[ii+1] - s_z[ii];
            float bn = sqrtf(bx*bx + by*by + bz*bz + 1e-12f);
            float bb = (bn > 3.6f && bn < 4.0f) ? 1.f : 0.f;
            float u1x = bx*bb, u1y = by*bb, u1z = bz*bb;
            float rn1 = rsqrtf(u1x*u1x + u1y*u1y + u1z*u1z + 1e-12f);
            u1x *= rn1; u1y *= rn1; u1z *= rn1;

            float n2x = u2y*u1z - u2z*u1y;
            float n2y = u2z*u1x - u2x*u1z;
            float n2z = u2x*u1y - u2y*u1x;
            float rnn = rsqrtf(n2x*n2x + n2y*n2y + n2z*n2z + 1e-12f);
            n2x *= rnn; n2y *= rnn; n2z *= rnn;

            float o1x = u2x - u1x, o1y = u2y - u1y, o1z = u2z - u1z;
            float rno = rsqrtf(o1x*o1x + o1y*o1y + o1z*o1z + 1e-12f);
            o1x *= rno; o1y *= rno; o1z *= rno;

            O[0] = o1x; O[1] = o1y; O[2] = o1z;
            O[3] = n2x; O[4] = n2y; O[5] = n2z;
            O[6] = o1y*n2z - o1z*n2y;
            O[7] = o1z*n2x - o1x*n2z;
            O[8] = o1x*n2y - o1y*n2x;
        }
    }

    int r = r0 + warp;
    int i = r - b * Lc;

    float cix = s_x[i], ciy = s_y[i], ciz = s_z[i];
    float mi  = s_m[i];

    float d[NSLOT];
    unsigned long long valid = 0ull;
    float dmax = 0.f;
    #pragma unroll
    for (int s = 0; s < NSLOT; s++) {
        int j = s * 32 + lane;
        float dx = s_x[j] - cix;
        float dy = s_y[j] - ciy;
        float dz = s_z[j] - ciz;
        float dist = sqrtf(dx*dx + dy*dy + dz*dz + 1e-6f);
        float m2 = mi * s_m[j];
        float D = m2 * dist;
        d[s] = D;
        if (m2 != 0.f) valid |= (1ull << s);
        dmax = fmaxf(dmax, D);
    }
    #pragma unroll
    for (int o = 16; o; o >>= 1)
        dmax = fmaxf(dmax, __shfl_xor_sync(0xffffffffu, dmax, o));
    #pragma unroll
    for (int s = 0; s < NSLOT; s++)
        if (!((valid >> s) & 1ull)) d[s] = dmax;

    // build 6 group mins (8 slots each), then lane best
    ull g[6];
    #pragma unroll
    for (int gg = 0; gg < 6; gg++) {
        ull m = ~0ull;
        #pragma unroll
        for (int s2 = 0; s2 < 8; s2++) {
            int s = gg * 8 + s2;
            ull key = ((ull)__float_as_uint(d[s]) << 32) | (unsigned)(s * 32 + lane);
            if (key < m) m = key;
        }
        g[gg] = m;
    }
    ull lb = g[0];
    #pragma unroll
    for (int gg = 1; gg < 6; gg++) if (g[gg] < lb) lb = g[gg];

    unsigned long long removed = 0ull;
    for (int t = 0; t < Kc; t++) {
        ull best = lb;
        #pragma unroll
        for (int o = 16; o; o >>= 1) {
            ull oth = __shfl_xor_sync(0xffffffffu, best, o);
            if (oth < best) best = oth;
        }
        int j = (int)(best & 0xffffffffull);
        float val = __uint_as_float((unsigned)(best >> 32));
        if (lane == 0) {
            g_Eidx[(size_t)r * Kc + t] = j;
            g_Dn  [(size_t)r * Kc + t] = val;
            long long off = (long long)Bc * Lc * Kc * EF + (long long)r * Kc + t;
            if (off < out_elems) out[off] = (float)j;   // E_idx as float
        }
        if ((j & 31) == lane) {
            int s = j >> 5;
            removed |= (1ull << s);
            int grp = s >> 3;
            #pragma unroll
            for (int gg = 0; gg < 6; gg++) {
                if (gg == grp) {
                    ull m = ~0ull;
                    #pragma unroll
                    for (int s2 = 0; s2 < 8; s2++) {
                        int s3 = gg * 8 + s2;
                        if (!((removed >> s3) & 1ull)) {
                            ull key = ((ull)__float_as_uint(d[s3]) << 32) |
                                      (unsigned)(s3 * 32 + lane);
                            if (key < m) m = key;
                        }
                    }
                    g[gg] = m;
                }
            }
            lb = g[0];
            #pragma unroll
            for (int gg = 1; gg < 6; gg++) if (g[gg] < lb) lb = g[gg];
        }
    }
}

// ---------------------------------------------------------------------------
// Kernel 2: persistent, 592 blocks x 128 threads; each block loops over
// ~10 nodes. Per node: features -> f32x2 GEMM (4 warps x 8 edges x 4 feats)
// -> fused LayerNorm epilogue. Exact R12 phase structure inside the loop;
// persistence desyncs co-resident blocks so MUFU/feature phases overlap
// other blocks' fma-heavy GEMM.
// ---------------------------------------------------------------------------
__device__ __forceinline__ float fsign(float x)
{
    return (float)((x > 0.f) - (x < 0.f));
}

__global__ void __launch_bounds__(128, 4)
k_edge(const float* __restrict__ Ca,
       const int* __restrict__ ridx, const int* __restrict__ chain,
       const float* __restrict__ gamma, const float* __restrict__ beta,
       float* __restrict__ out, long long out_elems)
{
    __shared__ __align__(16) float s_feat[32][KPAD];   // 19456 B
    __shared__ float s_dist[Kc][10];
    __shared__ float s_misc[18];        // O_i(9), ci(3)@9, cim(3)@12, cip(3)@15
    __shared__ int   s_dpos[32];
    __shared__ int   s_j[32];
    __shared__ int   s_ri, s_ch;

    int tid = threadIdx.x;

    // ---- one-time inits (pad column, dummy dpos) ----
    if (tid >= 64 && tid < 96) {
        s_feat[tid - 64][151] = 0.f;   // pad column (weight is 0 but avoid NaN*0)
    } else if (tid >= 32 && tid < 64) {
        s_dpos[tid - 32] = 0;          // entries 30/31 stay 0 forever
    }

    for (int r = blockIdx.x; r < Bc * Lc; r += NEDGE_BLOCKS) {
        int b = r / Lc, i = r - b * Lc;
        const float* cab = Ca + (size_t)b * Lc * 3;

        // protect smem from previous iteration's GEMM readers,
        // and order the one-time inits on the first iteration
        __syncthreads();

        // ---- phase 1: stage misc, edge indices ----
        if (tid < 9) s_misc[tid] = g_O[(size_t)r * 9 + tid];
        else if (tid < 18) {
            int c = tid - 9;
            float v;
            if (c < 3)       v = cab[i*3 + c];
            else if (c < 6)  v = (i > 0)      ? cab[(i-1)*3 + (c-3)] : 0.f;
            else             v = (i < Lc - 1) ? cab[(i+1)*3 + (c-6)] : 0.f;
            s_misc[tid] = v;
        }
        else if (tid == 18) s_ri = ridx[r];
        else if (tid == 19) s_ch = chain[r];
        else if (tid >= 32 && tid < 64) {
            int e = tid - 32;
            if (e < Kc) s_j[e] = g_Eidx[(size_t)r * Kc + e];
        }
        __syncthreads();

        // ---- phase 2: geometry (threads 0..29) || distances (threads 32..127)
        if (tid < Kc) {
            int e = tid;
            int j = s_j[e];
            const float* Oi  = &s_misc[0];
            const float* ci  = &s_misc[9];

            float cjx = cab[j*3+0], cjy = cab[j*3+1], cjz = cab[j*3+2];

            // positional embedding index
            int off = s_ri - ridx[(size_t)b * Lc + j];
            int ech = (s_ch == chain[(size_t)b * Lc + j]);
            s_dpos[e] = ech ? min(max(off + 32, 0), 64) : 65;

            // dU = norml(O_i @ (Ca_j - Ca_i))  -> dims 144..146
            float vx = cjx-ci[0], vy = cjy-ci[1], vz = cjz-ci[2];
            float w0 = Oi[0]*vx + Oi[1]*vy + Oi[2]*vz;
            float w1 = Oi[3]*vx + Oi[4]*vy + Oi[5]*vz;
            float w2 = Oi[6]*vx + Oi[7]*vy + Oi[8]*vz;
            float rn = rsqrtf(w0*w0 + w1*w1 + w2*w2 + 1e-12f);
            s_feat[e][144] = w0*rn; s_feat[e][145] = w1*rn; s_feat[e][146] = w2*rn;

            // R = O_i^T @ O_j ; quaternion -> dims 147..150
            float Oj[9];
            #pragma unroll
            for (int t = 0; t < 9; t++) Oj[t] = g_O[((size_t)b * Lc + j) * 9 + t];
            float R[3][3];
            #pragma unroll
            for (int a2 = 0; a2 < 3; a2++)
                #pragma unroll
                for (int m = 0; m < 3; m++)
                    R[a2][m] = Oi[0*3+a2]*Oj[0*3+m] + Oi[1*3+a2]*Oj[1*3+m] + Oi[2*3+a2]*Oj[2*3+m];
            float Rxx = R[0][0], Ryy = R[1][1], Rzz = R[2][2];
            float mx = 0.5f * sqrtf(fabsf(1.f + Rxx - Ryy - Rzz) + 1e-12f);
            float my = 0.5f * sqrtf(fabsf(1.f - Rxx + Ryy - Rzz) + 1e-12f);
            float mz = 0.5f * sqrtf(fabsf(1.f - Rxx - Ryy + Rzz) + 1e-12f);
            float qx = fsign(R[2][1] - R[1][2]) * mx;
            float qy = fsign(R[0][2] - R[2][0]) * my;
            float qz = fsign(R[1][0] - R[0][1]) * mz;
            float qw = 0.5f * sqrtf(fmaxf(1.f + Rxx + Ryy + Rzz, 0.f) + 1e-12f);
            float qn = rsqrtf(qx*qx + qy*qy + qz*qz + qw*qw + 1e-12f);
            s_feat[e][147] = qx*qn; s_feat[e][148] = qy*qn;
            s_feat[e][149] = qz*qn; s_feat[e][150] = qw*qn;
        } else if (tid >= 32) {
            // 96 threads cover 270 distance items (e*9+q)
            for (int idx = tid - 32; idx < Kc * 9; idx += 96) {
                int e = idx / 9, q = idx - e * 9;
                float v;
                if (q == 0) {
                    v = g_Dn[(size_t)r * Kc + e];
                } else {
                    const float* a = &s_misc[c_aoff[q]];
                    int bo = c_boff[q];
                    int j = s_j[e];
                    float bx = 0.f, by = 0.f, bz = 0.f;
                    bool zero = (bo == -1 && j == 0) || (bo == 1 && j == Lc - 1);
                    if (!zero) {
                        int jb = j + bo;
                        bx = cab[jb*3+0]; by = cab[jb*3+1]; bz = cab[jb*3+2];
                    }
                    float dx = a[0]-bx, dy = a[1]-by, dz = a[2]-bz;
                    v = sqrtf(dx*dx + dy*dy + dz*dz + 1e-6f);
                }
                s_dist[e][q] = v;
            }
        }
        __syncthreads();

        // ---- phase 3: RBFs (30 edges x 9 dists x 16 mus -> dims 0..143) ----
        for (int idx = tid; idx < Kc * 144; idx += 128) {
            int e = idx / 144;
            int rem = idx - e * 144;
            int rr = rem >> 4;
            int m = rem & 15;
            float D = s_dist[e][rr];
            float mu = 2.0f + (4.0f / 3.0f) * (float)m;
            float t = (D - mu) * 0.8f;
            s_feat[e][rem] = __expf(-t * t);
        }
        __syncthreads();

        // ---- phase 4: f32x2 GEMM + fused LayerNorm epilogue ----
        {
            int h  = tid >> 5;          // warp = edge group 0..3 -> edges h*8..h*8+7
            int fq = tid & 31;          // feature base lane
            const char* fbase = (const char*)&s_feat[h * 8][0];
            const ull* wk = g_WK + fq;

            ull acc[8][4];
            #pragma unroll
            for (int e8 = 0; e8 < 8; e8++) {
                int d = s_dpos[h * 8 + e8];
                #pragma unroll
                for (int q = 0; q < 4; q++)
                    acc[e8][q] = (ull)__float_as_uint(g_T[d * EF + fq + 32 * q]);
            }

            for (int kg = 0; kg < KG; kg++) {
                const ull* w0p = wk + (size_t)(2 * kg) * EF;
                ull w0[4], w1[4];
                #pragma unroll
                for (int q = 0; q < 4; q++) {
                    w0[q] = w0p[32 * q];
                    w1[q] = w0p[EF + 32 * q];
                }
                const char* fk = fbase + 16 * kg;
                #pragma unroll
                for (int e8 = 0; e8 < 8; e8++) {
                    ulonglong2 fe = *(const ulonglong2*)(fk + e8 * (KPAD * 4));
                    #pragma unroll
                    for (int q = 0; q < 4; q++) FMA_F32X2(acc[e8][q], fe.x, w0[q]);
                    #pragma unroll
                    for (int q = 0; q < 4; q++) FMA_F32X2(acc[e8][q], fe.y, w1[q]);
                }
            }

            // fused LN epilogue: warp holds all 128 features of each edge
            float gm[4], bt[4];
            #pragma unroll
            for (int q = 0; q < 4; q++) {
                gm[q] = gamma[fq + 32 * q];
                bt[q] = beta[fq + 32 * q];
            }

            #pragma unroll
            for (int e8 = 0; e8 < 8; e8++) {
                int e = h * 8 + e8;
                if (e < Kc) {
                    float v[4];
                    #pragma unroll
                    for (int q = 0; q < 4; q++) {
                        float lo = __uint_as_float((unsigned)(acc[e8][q] & 0xffffffffull));
                        float hi = __uint_as_float((unsigned)(acc[e8][q] >> 32));
                        v[q] = lo + hi;
                    }
                    float sum = v[0] + v[1] + v[2] + v[3];
                    #pragma unroll
                    for (int o = 16; o; o >>= 1) sum += __shfl_xor_sync(0xffffffffu, sum, o);
                    float mu = sum * (1.f / 128.f);
                    float ss = 0.f;
                    #pragma unroll
                    for (int q = 0; q < 4; q++) { float dv = v[q] - mu; ss += dv * dv; }
                    #pragma unroll
                    for (int o = 16; o; o >>= 1) ss += __shfl_xor_sync(0xffffffffu, ss, o);
                    float var = ss * (1.f / 128.f);
                    float rstd = rsqrtf(var + 1e-5f);
                    long long base = ((long long)r * Kc + e) * EF;
                    #pragma unroll
                    for (int q = 0; q < 4; q++) {
                        long long o2 = base + fq + 32 * q;
                        if (o2 < out_elems)
                            out[o2] = (v[q] - mu) * rstd * gm[q] + bt[q];
                    }
                }
            }
        }
    }
}

// ---------------------------------------------------------------------------
extern "C" void kernel_launch(void* const* d_in, const int* in_sizes, int n_in,
                              void* d_out, int out_size)
{
    const float* Ca     = (const float*)d_in[0];
    const float* mask   = (const float*)d_in[1];
    const int*   ridx   = (const int*)  d_in[2];
    const int*   chain  = (const int*)  d_in[3];
    const float* W_pos  = (const float*)d_in[4];
    const float* b_pos  = (const float*)d_in[5];
    const float* W_edge = (const float*)d_in[6];
    const float* gamma  = (const float*)d_in[7];
    const float* beta   = (const float*)d_in[8];
    float* out = (float*)d_out;
    long long out_elems = (long long)out_size;

    k_topk<<<NTOPK + NPREP, 256>>>(Ca, mask, W_edge, W_pos, b_pos, out, out_elems);
    k_edge<<<NEDGE_BLOCKS, 128>>>(Ca, ridx, chain, gamma, beta, out, out_elems);
}

// round 16
// speedup vs baseline: 1.0067x; 1.0067x over previous
#include <cuda_runtime.h>
#include <cuda_bf16.h>
#include <math.h>

#define Bc 4
#define Lc 1536
#define Kc 30
#define EF 128
#define EIN 167
#define NSLOT 48   // Lc / 32

// GEMM k-dim after removing 16 pos dims: 151, padded to 152 = 76 k-pairs
#define KD 151
#define KPAD 152
#define KG 38      // 4-k groups

#define NTOPK (Bc*Lc/8)          // 768 topk blocks
#define PREP_TOTAL ((KPAD/2)*EF + 66*EF)
#define NPREP ((PREP_TOTAL + 255)/256)   // 71 prep blocks
#define NEDGE 296                // producer/consumer blocks (2/SM target)

typedef unsigned long long ull;

// packed f32x2 FMA: acc.{lo,hi} += a.{lo,hi} * b.{lo,hi}
#define FMA_F32X2(acc, a, b) \
    asm("fma.rn.f32x2 %0, %1, %2, %0;" : "+l"(acc) : "l"(a), "l"(b))

// named-barrier helpers (warp-uniform call sites only)
#define BAR_SYNC_256(id)   asm volatile("bar.sync %0, 256;"   :: "r"(id) : "memory")
#define BAR_ARRIVE_256(id) asm volatile("bar.arrive %0, 256;" :: "r"(id) : "memory")
#define PBAR()             asm volatile("bar.sync 5, 128;" ::: "memory")

// scratch (device globals; no allocation allowed)
__device__ float g_O[Bc*Lc*9];
__device__ int   g_Eidx[Bc*Lc*Kc];
__device__ float g_Dn[Bc*Lc*Kc];
__device__ __align__(16) ull g_WK[(KPAD/2)*EF];  // g_WK[kp][f] = {W[f][16+2kp], W[f][16+2kp+1]}
__device__ float g_T[66*EF];        // T[d][f] = sum_p (W_pos[p][d]+b_pos[p]) * W_edge[f][p]

// dist-pair maps: q=1..8 -> a-side base in s_misc, b-side offset
__device__ const int c_aoff[9] = {0, 12, 15, 12, 12, 9, 9, 15, 15};
__device__ const int c_boff[9] = {0, -1,  1,  0,  1, -1, 1, -1,  0};

// ---------------------------------------------------------------------------
// Kernel 1: [merged] prep blocks (>= NTOPK) + top-K/frames blocks (< NTOPK)
// ---------------------------------------------------------------------------
__global__ void __launch_bounds__(256)
k_topk(const float* __restrict__ Ca, const float* __restrict__ mask,
       const float* __restrict__ W, const float* __restrict__ W_pos,
       const float* __restrict__ b_pos,
       float* __restrict__ out, long long out_elems)
{
    int tid  = threadIdx.x;

    // ---------------- prep path (71 trailing blocks) ----------------
    if (blockIdx.x >= NTOPK) {
        int idx = (blockIdx.x - NTOPK) * 256 + tid;
        const int NW = (KPAD/2) * EF;    // 9728
        if (idx < NW) {
            int kp = idx >> 7;
            int f  = idx & (EF - 1);
            int k0 = 2 * kp, k1 = 2 * kp + 1;
            float w0 = (k0 < KD) ? W[f * EIN + 16 + k0] : 0.f;
            float w1 = (k1 < KD) ? W[f * EIN + 16 + k1] : 0.f;
            g_WK[idx] = ((ull)__float_as_uint(w1) << 32) | (ull)__float_as_uint(w0);
        } else {
            int j = idx - NW;            // 66*128 entries
            if (j < 66 * EF) {
                int d = j >> 7;
                int f = j & (EF - 1);
                float acc = 0.f;
                #pragma unroll
                for (int p = 0; p < 16; p++)
                    acc += (W_pos[p * 66 + d] + b_pos[p]) * W[f * EIN + p];
                g_T[d * EF + f] = acc;
            }
        }
        return;
    }

    // ---------------- top-K + frames path ----------------
    __shared__ float s_x[Lc], s_y[Lc], s_z[Lc], s_m[Lc];

    int warp = tid >> 5;
    int lane = tid & 31;
    int r0 = blockIdx.x * 8;
    int b  = r0 / Lc;
    const float* cab = Ca + (size_t)b * Lc * 3;
    const float* mb  = mask + (size_t)b * Lc;

    for (int idx = tid; idx < Lc; idx += 256) {
        s_x[idx] = cab[idx*3+0];
        s_y[idx] = cab[idx*3+1];
        s_z[idx] = cab[idx*3+2];
        s_m[idx] = mb[idx];
    }
    __syncthreads();

    // ---- fused frames for the block's 8 rows (threads 0..7) ----
    if (tid < 8) {
        int rr = r0 + tid;
        int ii = rr - b * Lc;
        float* O = &g_O[(size_t)rr * 9];
        if (ii < 1 || ii > Lc - 3) {
            #pragma unroll
            for (int t = 0; t < 9; t++) O[t] = 0.f;
        } else {
            float ax = s_x[ii] - s_x[ii-1], ay = s_y[ii] - s_y[ii-1], az = s_z[ii] - s_z[ii-1];
            float an = sqrtf(ax*ax + ay*ay + az*az + 1e-12f);
            float ab = (an > 3.6f && an < 4.0f) ? 1.f : 0.f;
            float u2x = ax*ab, u2y = ay*ab, u2z = az*ab;
            float rn2 = rsqrtf(u2x*u2x + u2y*u2y + u2z*u2z + 1e-12f);
            u2x *= rn2; u2y *= rn2; u2z *= rn2;

            float bx = s_x[ii+1] - s_x[ii], by = s_y[ii+1] - s_y[ii], bz = s_z[ii+1] - s_z[ii];
            float bn = sqrtf(bx*bx + by*by + bz*bz + 1e-12f);
            float bb = (bn > 3.6f && bn < 4.0f) ? 1.f : 0.f;
            float u1x = bx*bb, u1y = by*bb, u1z = bz*bb;
            float rn1 = rsqrtf(u1x*u1x + u1y*u1y + u1z*u1z + 1e-12f);
            u1x *= rn1; u1y *= rn1; u1z *= rn1;

            float n2x = u2y*u1z - u2z*u1y;
            float n2y = u2z*u1x - u2x*u1z;
            float n2z = u2x*u1y - u2y*u1x;
            float rnn = rsqrtf(n2x*n2x + n2y*n2y + n2z*n2z + 1e-12f);
            n2x *= rnn; n2y *= rnn; n2z *= rnn;

            float o1x = u2x - u1x, o1y = u2y - u1y, o1z = u2z - u1z;
            float rno = rsqrtf(o1x*o1x + o1y*o1y + o1z*o1z + 1e-12f);
            o1x *= rno; o1y *= rno; o1z *= rno;

            O[0] = o1x; O[1] = o1y; O[2] = o1z;
            O[3] = n2x; O[4] = n2y; O[5] = n2z;
            O[6] = o1y*n2z - o1z*n2y;
            O[7] = o1z*n2x - o1x*n2z;
            O[8] = o1x*n2y - o1y*n2x;
        }
    }

    int r = r0 + warp;
    int i = r - b * Lc;

    float cix = s_x[i], ciy = s_y[i], ciz = s_z[i];
    float mi  = s_m[i];

    float d[NSLOT];
    unsigned long long valid = 0ull;
    float dmax = 0.f;
    #pragma unroll
    for (int s = 0; s < NSLOT; s++) {
        int j = s * 32 + lane;
        float dx = s_x[j] - cix;
        float dy = s_y[j] - ciy;
        float dz = s_z[j] - ciz;
        float dist = sqrtf(dx*dx + dy*dy + dz*dz + 1e-6f);
        float m2 = mi * s_m[j];
        float D = m2 * dist;
        d[s] = D;
        if (m2 != 0.f) valid |= (1ull << s);
        dmax = fmaxf(dmax, D);
    }
    #pragma unroll
    for (int o = 16; o; o >>= 1)
        dmax = fmaxf(dmax, __shfl_xor_sync(0xffffffffu, dmax, o));
    #pragma unroll
    for (int s = 0; s < NSLOT; s++)
        if (!((valid >> s) & 1ull)) d[s] = dmax;

    // build 6 group mins (8 slots each), then lane best
    ull g[6];
    #pragma unroll
    for (int gg = 0; gg < 6; gg++) {
        ull m = ~0ull;
        #pragma unroll
        for (int s2 = 0; s2 < 8; s2++) {
            int s = gg * 8 + s2;
            ull key = ((ull)__float_as_uint(d[s]) << 32) | (unsigned)(s * 32 + lane);
            if (key < m) m = key;
        }
        g[gg] = m;
    }
    ull lb = g[0];
    #pragma unroll
    for (int gg = 1; gg < 6; gg++) if (g[gg] < lb) lb = g[gg];

    unsigned long long removed = 0ull;
    for (int t = 0; t < Kc; t++) {
        ull best = lb;
        #pragma unroll
        for (int o = 16; o; o >>= 1) {
            ull oth = __shfl_xor_sync(0xffffffffu, best, o);
            if (oth < best) best = oth;
        }
        int j = (int)(best & 0xffffffffull);
        float val = __uint_as_float((unsigned)(best >> 32));
        if (lane == 0) {
            g_Eidx[(size_t)r * Kc + t] = j;
            g_Dn  [(size_t)r * Kc + t] = val;
            long long off = (long long)Bc * Lc * Kc * EF + (long long)r * Kc + t;
            if (off < out_elems) out[off] = (float)j;   // E_idx as float
        }
        if ((j & 31) == lane) {
            int s = j >> 5;
            removed |= (1ull << s);
            int grp = s >> 3;
            #pragma unroll
            for (int gg = 0; gg < 6; gg++) {
                if (gg == grp) {
                    ull m = ~0ull;
                    #pragma unroll
                    for (int s2 = 0; s2 < 8; s2++) {
                        int s3 = gg * 8 + s2;
                        if (!((removed >> s3) & 1ull)) {
                            ull key = ((ull)__float_as_uint(d[s3]) << 32) |
                                      (unsigned)(s3 * 32 + lane);
                            if (key < m) m = key;
                        }
                    }
                    g[gg] = m;
                }
            }
            lb = g[0];
            #pragma unroll
            for (int gg = 1; gg < 6; gg++) if (g[gg] < lb) lb = g[gg];
        }
    }
}

// ---------------------------------------------------------------------------
// Kernel 2: warp-specialized producer/consumer pipeline. 296 blocks x 256
// threads. Warps 0-3 = consumers (f32x2 GEMM + fused LN, R12 code). Warps
// 4-7 = producers (feature phases, R12 code). Double-buffered s_feat/s_dpos;
// named barriers: ids 1,2 = full[buf], 3,4 = empty[buf], 5 = producer sync.
// Producers build node n+1 features while consumers run node n's GEMM.
// ---------------------------------------------------------------------------
__device__ __forceinline__ float fsign(float x)
{
    return (float)((x > 0.f) - (x < 0.f));
}

__global__ void __launch_bounds__(256)
k_edge(const float* __restrict__ Ca,
       const int* __restrict__ ridx, const int* __restrict__ chain,
       const float* __restrict__ gamma, const float* __restrict__ beta,
       float* __restrict__ out, long long out_elems)
{
    __shared__ __align__(16) float s_feat[2][32][KPAD];  // 38912 B
    __shared__ float s_dist[Kc][10];
    __shared__ float s_misc[18];        // O_i(9), ci(3)@9, cim(3)@12, cip(3)@15
    __shared__ int   s_dpos[2][32];
    __shared__ int   s_j[32];
    __shared__ int   s_ri, s_ch;

    int tid = threadIdx.x;
    int is_prod = tid >> 7;             // warps 4-7 produce
    int ptid = tid & 127;

    if (!is_prod) {
        // consumers pre-arrive both empty barriers so producers can start
        BAR_ARRIVE_256(3u);
        BAR_ARRIVE_256(4u);
    } else {
        // one-time inits: pad column + dummy dpos rows, both buffers
        if (ptid < 64) {
            int bb = ptid >> 5, e = ptid & 31;
            s_feat[bb][e][151] = 0.f;
            if (e >= Kc) s_dpos[bb][e] = 0;
        }
    }

    int buf = 0;
    for (int r = blockIdx.x; r < Bc * Lc; r += NEDGE) {
        int b = r / Lc, i = r - b * Lc;
        const float* cab = Ca + (size_t)b * Lc * 3;

        if (is_prod) {
            BAR_SYNC_256(3u + (unsigned)buf);   // wait buffer empty

            // ---- phase 1: stage misc, edge indices ----
            if (ptid < 9) s_misc[ptid] = g_O[(size_t)r * 9 + ptid];
            else if (ptid < 18) {
                int c = ptid - 9;
                float v;
                if (c < 3)       v = cab[i*3 + c];
                else if (c < 6)  v = (i > 0)      ? cab[(i-1)*3 + (c-3)] : 0.f;
                else             v = (i < Lc - 1) ? cab[(i+1)*3 + (c-6)] : 0.f;
                s_misc[ptid] = v;
            }
            else if (ptid == 18) s_ri = ridx[r];
            else if (ptid == 19) s_ch = chain[r];
            else if (ptid >= 32 && ptid < 64) {
                int e = ptid - 32;
                if (e < Kc) s_j[e] = g_Eidx[(size_t)r * Kc + e];
            }
            PBAR();

            // ---- phase 2: geometry (ptid<30) || distances (ptid>=32) ----
            if (ptid < Kc) {
                int e = ptid;
                int j = s_j[e];
                const float* Oi  = &s_misc[0];
                const float* ci  = &s_misc[9];

                float cjx = cab[j*3+0], cjy = cab[j*3+1], cjz = cab[j*3+2];

                int off = s_ri - ridx[(size_t)b * Lc + j];
                int ech = (s_ch == chain[(size_t)b * Lc + j]);
                s_dpos[buf][e] = ech ? min(max(off + 32, 0), 64) : 65;

                // dU -> dims 144..146
                float vx = cjx-ci[0], vy = cjy-ci[1], vz = cjz-ci[2];
                float w0 = Oi[0]*vx + Oi[1]*vy + Oi[2]*vz;
                float w1 = Oi[3]*vx + Oi[4]*vy + Oi[5]*vz;
                float w2 = Oi[6]*vx + Oi[7]*vy + Oi[8]*vz;
                float rn = rsqrtf(w0*w0 + w1*w1 + w2*w2 + 1e-12f);
                s_feat[buf][e][144] = w0*rn;
                s_feat[buf][e][145] = w1*rn;
                s_feat[buf][e][146] = w2*rn;

                // quaternion -> dims 147..150
                float Oj[9];
                #pragma unroll
                for (int t = 0; t < 9; t++) Oj[t] = g_O[((size_t)b * Lc + j) * 9 + t];
                float R[3][3];
                #pragma unroll
                for (int a2 = 0; a2 < 3; a2++)
                    #pragma unroll
                    for (int m = 0; m < 3; m++)
                        R[a2][m] = Oi[0*3+a2]*Oj[0*3+m] + Oi[1*3+a2]*Oj[1*3+m] + Oi[2*3+a2]*Oj[2*3+m];
                float Rxx = R[0][0], Ryy = R[1][1], Rzz = R[2][2];
                float mx = 0.5f * sqrtf(fabsf(1.f + Rxx - Ryy - Rzz) + 1e-12f);
                float my = 0.5f * sqrtf(fabsf(1.f - Rxx + Ryy - Rzz) + 1e-12f);
                float mz = 0.5f * sqrtf(fabsf(1.f - Rxx - Ryy + Rzz) + 1e-12f);
                float qx = fsign(R[2][1] - R[1][2]) * mx;
                float qy = fsign(R[0][2] - R[2][0]) * my;
                float qz = fsign(R[1][0] - R[0][1]) * mz;
                float qw = 0.5f * sqrtf(fmaxf(1.f + Rxx + Ryy + Rzz, 0.f) + 1e-12f);
                float qn = rsqrtf(qx*qx + qy*qy + qz*qz + qw*qw + 1e-12f);
                s_feat[buf][e][147] = qx*qn; s_feat[buf][e][148] = qy*qn;
                s_feat[buf][e][149] = qz*qn; s_feat[buf][e][150] = qw*qn;
            } else if (ptid >= 32) {
                // 96 threads cover 270 distance items (e*9+q)
                for (int idx = ptid - 32; idx < Kc * 9; idx += 96) {
                    int e = idx / 9, q = idx - e * 9;
                    float v;
                    if (q == 0) {
                        v = g_Dn[(size_t)r * Kc + e];
                    } else {
                        const float* a = &s_misc[c_aoff[q]];
                        int bo = c_boff[q];
                        int j = s_j[e];
                        float bx = 0.f, by = 0.f, bz = 0.f;
                        bool zero = (bo == -1 && j == 0) || (bo == 1 && j == Lc - 1);
                        if (!zero) {
                            int jb = j + bo;
                            bx = cab[jb*3+0]; by = cab[jb*3+1]; bz = cab[jb*3+2];
                        }
                        float dx = a[0]-bx, dy = a[1]-by, dz = a[2]-bz;
                        v = sqrtf(dx*dx + dy*dy + dz*dz + 1e-6f);
                    }
                    s_dist[e][q] = v;
                }
            }
            PBAR();

            // ---- phase 3: RBFs -> dims 0..143 ----
            for (int idx = ptid; idx < Kc * 144; idx += 128) {
                int e = idx / 144;
                int rem = idx - e * 144;
                int rr = rem >> 4;
                int m = rem & 15;
                float D = s_dist[e][rr];
                float mu = 2.0f + (4.0f / 3.0f) * (float)m;
                float t = (D - mu) * 0.8f;
                s_feat[buf][e][rem] = __expf(-t * t);
            }
            __threadfence_block();
            BAR_ARRIVE_256(1u + (unsigned)buf);   // buffer full
        } else {
            BAR_SYNC_256(1u + (unsigned)buf);     // wait buffer full

            int h  = tid >> 5;          // consumer warp 0..3 -> edges h*8..h*8+7
            int fq = tid & 31;          // feature base lane
            const char* fbase = (const char*)&s_feat[buf][h * 8][0];
            const ull* wk = g_WK + fq;

            ull acc[8][4];
            #pragma unroll
            for (int e8 = 0; e8 < 8; e8++) {
                int d = s_dpos[buf][h * 8 + e8];
                #pragma unroll
                for (int q = 0; q < 4; q++)
                    acc[e8][q] = (ull)__float_as_uint(g_T[d * EF + fq + 32 * q]);
            }

            for (int kg = 0; kg < KG; kg++) {
                const ull* w0p = wk + (size_t)(2 * kg) * EF;
                ull w0[4], w1[4];
                #pragma unroll
                for (int q = 0; q < 4; q++) {
                    w0[q] = w0p[32 * q];
                    w1[q] = w0p[EF + 32 * q];
                }
                const char* fk = fbase + 16 * kg;
                #pragma unroll
                for (int e8 = 0; e8 < 8; e8++) {
                    ulonglong2 fe = *(const ulonglong2*)(fk + e8 * (KPAD * 4));
                    #pragma unroll
                    for (int q = 0; q < 4; q++) FMA_F32X2(acc[e8][q], fe.x, w0[q]);
                    #pragma unroll
                    for (int q = 0; q < 4; q++) FMA_F32X2(acc[e8][q], fe.y, w1[q]);
                }
            }

            // fused LN epilogue (warp holds all 128 features of each edge)
            float gm[4], bt[4];
            #pragma unroll
            for (int q = 0; q < 4; q++) {
                gm[q] = gamma[fq + 32 * q];
                bt[q] = beta[fq + 32 * q];
            }

            #pragma unroll
            for (int e8 = 0; e8 < 8; e8++) {
                int e = h * 8 + e8;
                if (e < Kc) {
                    float v[4];
                    #pragma unroll
                    for (int q = 0; q < 4; q++) {
                        float lo = __uint_as_float((unsigned)(acc[e8][q] & 0xffffffffull));
                        float hi = __uint_as_float((unsigned)(acc[e8][q] >> 32));
                        v[q] = lo + hi;
                    }
                    float sum = v[0] + v[1] + v[2] + v[3];
                    #pragma unroll
                    for (int o = 16; o; o >>= 1) sum += __shfl_xor_sync(0xffffffffu, sum, o);
                    float mu = sum * (1.f / 128.f);
                    float ss = 0.f;
                    #pragma unroll
                    for (int q = 0; q < 4; q++) { float dv = v[q] - mu; ss += dv * dv; }
                    #pragma unroll
                    for (int o = 16; o; o >>= 1) ss += __shfl_xor_sync(0xffffffffu, ss, o);
                    float var = ss * (1.f / 128.f);
                    float rstd = rsqrtf(var + 1e-5f);
                    long long base = ((long long)r * Kc + e) * EF;
                    #pragma unroll
                    for (int q = 0; q < 4; q++) {
                        long long o2 = base + fq + 32 * q;
                        if (o2 < out_elems)
                            out[o2] = (v[q] - mu) * rstd * gm[q] + bt[q];
                    }
                }
            }
            // all s_feat reads are data-depended by the epilogue above
            BAR_ARRIVE_256(3u + (unsigned)buf);   // buffer empty
        }
        buf ^= 1;
    }
}

// ---------------------------------------------------------------------------
extern "C" void kernel_launch(void* const* d_in, const int* in_sizes, int n_in,
                              void* d_out, int out_size)
{
    const float* Ca     = (const float*)d_in[0];
    const float* mask   = (const float*)d_in[1];
    const int*   ridx   = (const int*)  d_in[2];
    const int*   chain  = (const int*)  d_in[3];
    const float* W_pos  = (const float*)d_in[4];
    const float* b_pos  = (const float*)d_in[5];
    const float* W_edge = (const float*)d_in[6];
    const float* gamma  = (const float*)d_in[7];
    const float* beta   = (const float*)d_in[8];
    float* out = (float*)d_out;
    long long out_elems = (long long)out_size;

    k_topk<<<NTOPK + NPREP, 256>>>(Ca, mask, W_edge, W_pos, b_pos, out, out_elems);
    k_edge<<<NEDGE, 256>>>(Ca, ridx, chain, gamma, beta, out, out_elems);
}

// round 17
// speedup vs baseline: 1.1115x; 1.1041x over previous
#include <cuda_runtime.h>
#include <cuda_bf16.h>
#include <math.h>

#define Bc 4
#define Lc 1536
#define Kc 30
#define EF 128
#define EIN 167
#define NSLOT 48   // Lc / 32

// GEMM k-dim after removing 16 pos dims: 151, padded to 152 = 76 k-pairs
#define KD 151
#define KPAD 152
#define KG 38      // 4-k groups

#define NTOPK (Bc*Lc/8)          // 768 topk blocks
#define PREP_TOTAL ((KPAD/2)*EF + 66*EF)
#define NPREP ((PREP_TOTAL + 255)/256)   // 71 prep blocks

typedef unsigned long long ull;

// packed f32x2 FMA: acc.{lo,hi} += a.{lo,hi} * b.{lo,hi}
#define FMA_F32X2(acc, a, b) \
    asm("fma.rn.f32x2 %0, %1, %2, %0;" : "+l"(acc) : "l"(a), "l"(b))

// scratch (device globals; no allocation allowed)
__device__ float g_O[Bc*Lc*9];
__device__ int   g_Eidx[Bc*Lc*Kc];
__device__ float g_Dn[Bc*Lc*Kc];
__device__ __align__(16) ull g_WK[(KPAD/2)*EF];  // g_WK[kp][f] = {W[f][16+2kp], W[f][16+2kp+1]}
__device__ float g_T[66*EF];        // T[d][f] = sum_p (W_pos[p][d]+b_pos[p]) * W_edge[f][p]

// dist-pair maps: q=1..8 -> a-side base in s_misc, b-side offset
__device__ const int c_aoff[9] = {0, 12, 15, 12, 12, 9, 9, 15, 15};
__device__ const int c_boff[9] = {0, -1,  1,  0,  1, -1, 1, -1,  0};

// ---------------------------------------------------------------------------
// Kernel 1: [merged] prep blocks (>= NTOPK) + top-K/frames blocks (< NTOPK)
// Top-k selection uses hardware redux.sync (u32) twice per round:
// min over float bits (>=0 so bit order == value order), then min index
// among lanes holding that value — identical lexicographic (dist,idx) order.
// ---------------------------------------------------------------------------
__global__ void __launch_bounds__(256)
k_topk(const float* __restrict__ Ca, const float* __restrict__ mask,
       const float* __restrict__ W, const float* __restrict__ W_pos,
       const float* __restrict__ b_pos,
       float* __restrict__ out, long long out_elems)
{
    int tid  = threadIdx.x;

    // ---------------- prep path (71 trailing blocks) ----------------
    if (blockIdx.x >= NTOPK) {
        int idx = (blockIdx.x - NTOPK) * 256 + tid;
        const int NW = (KPAD/2) * EF;    // 9728
        if (idx < NW) {
            int kp = idx >> 7;
            int f  = idx & (EF - 1);
            int k0 = 2 * kp, k1 = 2 * kp + 1;
            float w0 = (k0 < KD) ? W[f * EIN + 16 + k0] : 0.f;
            float w1 = (k1 < KD) ? W[f * EIN + 16 + k1] : 0.f;
            g_WK[idx] = ((ull)__float_as_uint(w1) << 32) | (ull)__float_as_uint(w0);
        } else {
            int j = idx - NW;            // 66*128 entries
            if (j < 66 * EF) {
                int d = j >> 7;
                int f = j & (EF - 1);
                float acc = 0.f;
                #pragma unroll
                for (int p = 0; p < 16; p++)
                    acc += (W_pos[p * 66 + d] + b_pos[p]) * W[f * EIN + p];
                g_T[d * EF + f] = acc;
            }
        }
        return;
    }

    // ---------------- top-K + frames path ----------------
    __shared__ float s_x[Lc], s_y[Lc], s_z[Lc], s_m[Lc];

    int warp = tid >> 5;
    int lane = tid & 31;
    int r0 = blockIdx.x * 8;
    int b  = r0 / Lc;
    const float* cab = Ca + (size_t)b * Lc * 3;
    const float* mb  = mask + (size_t)b * Lc;

    for (int idx = tid; idx < Lc; idx += 256) {
        s_x[idx] = cab[idx*3+0];
        s_y[idx] = cab[idx*3+1];
        s_z[idx] = cab[idx*3+2];
        s_m[idx] = mb[idx];
    }
    __syncthreads();

    // ---- fused frames for the block's 8 rows (threads 0..7) ----
    if (tid < 8) {
        int rr = r0 + tid;
        int ii = rr - b * Lc;
        float* O = &g_O[(size_t)rr * 9];
        if (ii < 1 || ii > Lc - 3) {
            #pragma unroll
            for (int t = 0; t < 9; t++) O[t] = 0.f;
        } else {
            float ax = s_x[ii] - s_x[ii-1], ay = s_y[ii] - s_y[ii-1], az = s_z[ii] - s_z[ii-1];
            float an = sqrtf(ax*ax + ay*ay + az*az + 1e-12f);
            float ab = (an > 3.6f && an < 4.0f) ? 1.f : 0.f;
            float u2x = ax*ab, u2y = ay*ab, u2z = az*ab;
            float rn2 = rsqrtf(u2x*u2x + u2y*u2y + u2z*u2z + 1e-12f);
            u2x *= rn2; u2y *= rn2; u2z *= rn2;

            float bx = s_x[ii+1] - s_x[ii], by = s_y[ii+1] - s_y[ii], bz = s_z[ii+1] - s_z[ii];
            float bn = sqrtf(bx*bx + by*by + bz*bz + 1e-12f);
            float bb = (bn > 3.6f && bn < 4.0f) ? 1.f : 0.f;
            float u1x = bx*bb, u1y = by*bb, u1z = bz*bb;
            float rn1 = rsqrtf(u1x*u1x + u1y*u1y + u1z*u1z + 1e-12f);
            u1x *= rn1; u1y *= rn1; u1z *= rn1;

            float n2x = u2y*u1z - u2z*u1y;
            float n2y = u2z*u1x - u2x*u1z;
            float n2z = u2x*u1y - u2y*u1x;
            float rnn = rsqrtf(n2x*n2x + n2y*n2y + n2z*n2z + 1e-12f);
            n2x *= rnn; n2y *= rnn; n2z *= rnn;

            float o1x = u2x - u1x, o1y = u2y - u1y, o1z = u2z - u1z;
            float rno = rsqrtf(o1x*o1x + o1y*o1y + o1z*o1z + 1e-12f);
            o1x *= rno; o1y *= rno; o1z *= rno;

            O[0] = o1x; O[1] = o1y; O[2] = o1z;
            O[3] = n2x; O[4] = n2y; O[5] = n2z;
            O[6] = o1y*n2z - o1z*n2y;
            O[7] = o1z*n2x - o1x*n2z;
            O[8] = o1x*n2y - o1y*n2x;
        }
    }

    int r = r0 + warp;
    int i = r - b * Lc;

    float cix = s_x[i], ciy = s_y[i], ciz = s_z[i];
    float mi  = s_m[i];

    float d[NSLOT];
    unsigned long long valid = 0ull;
    float dmax = 0.f;
    #pragma unroll
    for (int s = 0; s < NSLOT; s++) {
        int j = s * 32 + lane;
        float dx = s_x[j] - cix;
        float dy = s_y[j] - ciy;
        float dz = s_z[j] - ciz;
        float dist = sqrtf(dx*dx + dy*dy + dz*dz + 1e-6f);
        float m2 = mi * s_m[j];
        float D = m2 * dist;
        d[s] = D;
        if (m2 != 0.f) valid |= (1ull << s);
        dmax = fmaxf(dmax, D);
    }
    // hardware warp max (D >= 0, bit order == value order)
    dmax = __uint_as_float(__reduce_max_sync(0xffffffffu, __float_as_uint(dmax)));
    #pragma unroll
    for (int s = 0; s < NSLOT; s++)
        if (!((valid >> s) & 1ull)) d[s] = dmax;

    // build 6 group mins (8 slots each), then lane best
    ull g[6];
    #pragma unroll
    for (int gg = 0; gg < 6; gg++) {
        ull m = ~0ull;
        #pragma unroll
        for (int s2 = 0; s2 < 8; s2++) {
            int s = gg * 8 + s2;
            ull key = ((ull)__float_as_uint(d[s]) << 32) | (unsigned)(s * 32 + lane);
            if (key < m) m = key;
        }
        g[gg] = m;
    }
    ull lb = g[0];
    #pragma unroll
    for (int gg = 1; gg < 6; gg++) if (g[gg] < lb) lb = g[gg];

    unsigned long long removed = 0ull;
    for (int t = 0; t < Kc; t++) {
        // two hardware reductions replace the 64-bit shfl tree
        unsigned bv = (unsigned)(lb >> 32);
        unsigned mn = __reduce_min_sync(0xffffffffu, bv);
        unsigned idxc = (bv == mn) ? (unsigned)(lb & 0xffffffffull) : 0xffffffffu;
        unsigned bi = __reduce_min_sync(0xffffffffu, idxc);
        int j = (int)bi;
        float val = __uint_as_float(mn);
        if (lane == 0) {
            g_Eidx[(size_t)r * Kc + t] = j;
            g_Dn  [(size_t)r * Kc + t] = val;
            long long off = (long long)Bc * Lc * Kc * EF + (long long)r * Kc + t;
            if (off < out_elems) out[off] = (float)j;   // E_idx as float
        }
        if ((j & 31) == lane) {
            int s = j >> 5;
            removed |= (1ull << s);
            int grp = s >> 3;
            #pragma unroll
            for (int gg = 0; gg < 6; gg++) {
                if (gg == grp) {
                    ull m = ~0ull;
                    #pragma unroll
                    for (int s2 = 0; s2 < 8; s2++) {
                        int s3 = gg * 8 + s2;
                        if (!((removed >> s3) & 1ull)) {
                            ull key = ((ull)__float_as_uint(d[s3]) << 32) |
                                      (unsigned)(s3 * 32 + lane);
                            if (key < m) m = key;
                        }
                    }
                    g[gg] = m;
                }
            }
            lb = g[0];
            #pragma unroll
            for (int gg = 1; gg < 6; gg++) if (g[gg] < lb) lb = g[gg];
        }
    }
}

// ---------------------------------------------------------------------------
// Kernel 2: fused per-(b,i), 128 threads: features -> f32x2 GEMM -> LN (regs)
// GEMM: 4 warps, each warp = 8 edges x all 128 features (4/thread).
// LayerNorm fused in the epilogue. (Exact R12 configuration — 224.6us.)
// ---------------------------------------------------------------------------
__device__ __forceinline__ float fsign(float x)
{
    return (float)((x > 0.f) - (x < 0.f));
}

__global__ void __launch_bounds__(128)
k_edge(const float* __restrict__ Ca,
       const int* __restrict__ ridx, const int* __restrict__ chain,
       const float* __restrict__ gamma, const float* __restrict__ beta,
       float* __restrict__ out, long long out_elems)
{
    __shared__ __align__(16) float s_feat[32][KPAD];   // 19456 B
    __shared__ float s_dist[Kc][10];
    __shared__ float s_misc[18];        // O_i(9), ci(3)@9, cim(3)@12, cip(3)@15
    __shared__ int   s_dpos[32];
    __shared__ int   s_j[32];
    __shared__ int   s_ri, s_ch;

    int r = blockIdx.x;
    int b = r / Lc, i = r - b * Lc;
    int tid = threadIdx.x;
    const float* cab = Ca + (size_t)b * Lc * 3;

    // ---- phase 1: stage misc, edge indices; zero only the k=151 pad column
    if (tid < 9) s_misc[tid] = g_O[(size_t)r * 9 + tid];
    else if (tid < 18) {
        int c = tid - 9;
        float v;
        if (c < 3)       v = cab[i*3 + c];
        else if (c < 6)  v = (i > 0)      ? cab[(i-1)*3 + (c-3)] : 0.f;
        else             v = (i < Lc - 1) ? cab[(i+1)*3 + (c-6)] : 0.f;
        s_misc[tid] = v;
    }
    else if (tid == 18) s_ri = ridx[r];
    else if (tid == 19) s_ch = chain[r];
    else if (tid >= 32 && tid < 64) {
        int e = tid - 32;
        s_j[e] = (e < Kc) ? g_Eidx[(size_t)r * Kc + e] : 0;
        s_dpos[e] = 0;
    }
    else if (tid >= 64 && tid < 96) {
        int e = tid - 64;
        s_feat[e][151] = 0.f;   // pad column (weight is 0 but avoid NaN*0)
    }
    __syncthreads();

    // ---- phase 2: geometry (threads 0..29) || distances (threads 32..127) ----
    if (tid < Kc) {
        int e = tid;
        int j = s_j[e];
        const float* Oi  = &s_misc[0];
        const float* ci  = &s_misc[9];

        float cjx = cab[j*3+0], cjy = cab[j*3+1], cjz = cab[j*3+2];

        // positional embedding index
        int off = s_ri - ridx[(size_t)b * Lc + j];
        int ech = (s_ch == chain[(size_t)b * Lc + j]);
        s_dpos[e] = ech ? min(max(off + 32, 0), 64) : 65;

        // dU = norml(O_i @ (Ca_j - Ca_i))  -> dims 144..146
        float vx = cjx-ci[0], vy = cjy-ci[1], vz = cjz-ci[2];
        float w0 = Oi[0]*vx + Oi[1]*vy + Oi[2]*vz;
        float w1 = Oi[3]*vx + Oi[4]*vy + Oi[5]*vz;
        float w2 = Oi[6]*vx + Oi[7]*vy + Oi[8]*vz;
        float rn = rsqrtf(w0*w0 + w1*w1 + w2*w2 + 1e-12f);
        s_feat[e][144] = w0*rn; s_feat[e][145] = w1*rn; s_feat[e][146] = w2*rn;

        // R = O_i^T @ O_j ; quaternion -> dims 147..150
        float Oj[9];
        #pragma unroll
        for (int t = 0; t < 9; t++) Oj[t] = g_O[((size_t)b * Lc + j) * 9 + t];
        float R[3][3];
        #pragma unroll
        for (int a2 = 0; a2 < 3; a2++)
            #pragma unroll
            for (int m = 0; m < 3; m++)
                R[a2][m] = Oi[0*3+a2]*Oj[0*3+m] + Oi[1*3+a2]*Oj[1*3+m] + Oi[2*3+a2]*Oj[2*3+m];
        float Rxx = R[0][0], Ryy = R[1][1], Rzz = R[2][2];
        float mx = 0.5f * sqrtf(fabsf(1.f + Rxx - Ryy - Rzz) + 1e-12f);
        float my = 0.5f * sqrtf(fabsf(1.f - Rxx + Ryy - Rzz) + 1e-12f);
        float mz = 0.5f * sqrtf(fabsf(1.f - Rxx - Ryy + Rzz) + 1e-12f);
        float qx = fsign(R[2][1] - R[1][2]) * mx;
        float qy = fsign(R[0][2] - R[2][0]) * my;
        float qz = fsign(R[1][0] - R[0][1]) * mz;
        float qw = 0.5f * sqrtf(fmaxf(1.f + Rxx + Ryy + Rzz, 0.f) + 1e-12f);
        float qn = rsqrtf(qx*qx + qy*qy + qz*qz + qw*qw + 1e-12f);
        s_feat[e][147] = qx*qn; s_feat[e][148] = qy*qn;
        s_feat[e][149] = qz*qn; s_feat[e][150] = qw*qn;
    } else if (tid >= 32) {
        // 96 threads cover 270 distance items (e*9+q)
        for (int idx = tid - 32; idx < Kc * 9; idx += 96) {
            int e = idx / 9, q = idx - e * 9;
            float v;
            if (q == 0) {
                v = g_Dn[(size_t)r * Kc + e];
            } else {
                const float* a = &s_misc[c_aoff[q]];
                int bo = c_boff[q];
                int j = s_j[e];
                float bx = 0.f, by = 0.f, bz = 0.f;
                bool zero = (bo == -1 && j == 0) || (bo == 1 && j == Lc - 1);
                if (!zero) {
                    int jb = j + bo;
                    bx = cab[jb*3+0]; by = cab[jb*3+1]; bz = cab[jb*3+2];
                }
                float dx = a[0]-bx, dy = a[1]-by, dz = a[2]-bz;
                v = sqrtf(dx*dx + dy*dy + dz*dz + 1e-6f);
            }
            s_dist[e][q] = v;
        }
    }
    __syncthreads();

    // ---- phase 3: RBFs (30 edges x 9 dists x 16 mus -> dims 0..143) ----
    for (int idx = tid; idx < Kc * 144; idx += 128) {
        int e = idx / 144;
        int rem = idx - e * 144;
        int rr = rem >> 4;
        int m = rem & 15;
        float D = s_dist[e][rr];
        float mu = 2.0f + (4.0f / 3.0f) * (float)m;
        float t = (D - mu) * 0.8f;
        s_feat[e][rem] = __expf(-t * t);
    }
    __syncthreads();

    // ---- phase 4: f32x2 GEMM + fused LayerNorm epilogue ----
    {
        int h  = tid >> 5;          // warp = edge group 0..3 -> edges h*8..h*8+7
        int fq = tid & 31;          // feature base lane
        const char* fbase = (const char*)&s_feat[h * 8][0];
        const ull* wk = g_WK + fq;

        ull acc[8][4];
        #pragma unroll
        for (int e8 = 0; e8 < 8; e8++) {
            int d = s_dpos[h * 8 + e8];
            #pragma unroll
            for (int q = 0; q < 4; q++)
                acc[e8][q] = (ull)__float_as_uint(g_T[d * EF + fq + 32 * q]);
        }

        for (int kg = 0; kg < KG; kg++) {
            const ull* w0p = wk + (size_t)(2 * kg) * EF;
            ull w0[4], w1[4];
            #pragma unroll
            for (int q = 0; q < 4; q++) {
                w0[q] = w0p[32 * q];
                w1[q] = w0p[EF + 32 * q];
            }
            const char* fk = fbase + 16 * kg;
            #pragma unroll
            for (int e8 = 0; e8 < 8; e8++) {
                ulonglong2 fe = *(const ulonglong2*)(fk + e8 * (KPAD * 4));
                #pragma unroll
                for (int q = 0; q < 4; q++) FMA_F32X2(acc[e8][q], fe.x, w0[q]);
                #pragma unroll
                for (int q = 0; q < 4; q++) FMA_F32X2(acc[e8][q], fe.y, w1[q]);
            }
        }

        // fused LN epilogue: warp holds all 128 features of each edge
        float gm[4], bt[4];
        #pragma unroll
        for (int q = 0; q < 4; q++) {
            gm[q] = gamma[fq + 32 * q];
            bt[q] = beta[fq + 32 * q];
        }

        #pragma unroll
        for (int e8 = 0; e8 < 8; e8++) {
            int e = h * 8 + e8;
            if (e < Kc) {
                float v[4];
                #pragma unroll
                for (int q = 0; q < 4; q++) {
                    float lo = __uint_as_float((unsigned)(acc[e8][q] & 0xffffffffull));
                    float hi = __uint_as_float((unsigned)(acc[e8][q] >> 32));
                    v[q] = lo + hi;
                }
                float sum = v[0] + v[1] + v[2] + v[3];
                #pragma unroll
                for (int o = 16; o; o >>= 1) sum += __shfl_xor_sync(0xffffffffu, sum, o);
                float mu = sum * (1.f / 128.f);
                float ss = 0.f;
                #pragma unroll
                for (int q = 0; q < 4; q++) { float dv = v[q] - mu; ss += dv * dv; }
                #pragma unroll
                for (int o = 16; o; o >>= 1) ss += __shfl_xor_sync(0xffffffffu, ss, o);
                float var = ss * (1.f / 128.f);
                float rstd = rsqrtf(var + 1e-5f);
                long long base = ((long long)r * Kc + e) * EF;
                #pragma unroll
                for (int q = 0; q < 4; q++) {
                    long long o2 = base + fq + 32 * q;
                    if (o2 < out_elems)
                        out[o2] = (v[q] - mu) * rstd * gm[q] + bt[q];
                }
            }
        }
    }
}

// ---------------------------------------------------------------------------
extern "C" void kernel_launch(void* const* d_in, const int* in_sizes, int n_in,
                              void* d_out, int out_size)
{
    const float* Ca     = (const float*)d_in[0];
    const float* mask   = (const float*)d_in[1];
    const int*   ridx   = (const int*)  d_in[2];
    const int*   chain  = (const int*)  d_in[3];
    const float* W_pos  = (const float*)d_in[4];
    const float* b_pos  = (const float*)d_in[5];
    const float* W_edge = (const float*)d_in[6];
    const float* gamma  = (const float*)d_in[7];
    const float* beta   = (const float*)d_in[8];
    float* out = (float*)d_out;
    long long out_elems = (long long)out_size;

    k_topk<<<NTOPK + NPREP, 256>>>(Ca, mask, W_edge, W_pos, b_pos, out, out_elems);
    k_edge<<<Bc * Lc, 128>>>(Ca, ridx, chain, gamma, beta, out, out_elems);
}